// round 10
// baseline (speedup 1.0000x reference)
#include <cuda_runtime.h>
#include <cuda_bf16.h>
#include <math.h>
#include <stdint.h>

// Problem constants
#define B_ 2
#define T_ 2048
#define C_ 2048
#define H_ 16
#define KVH_ 4
#define D_ 128
#define M_ (B_ * T_)          // 4096
#define KVC_ (KVH_ * D_)      // 512
#define SCALE_ 0.08838834764831845f
#define RMS_EPS 1.1920929e-07f

// ---------------------------------------------------------------------------
// Scratch (device globals; no allocation allowed)
// ---------------------------------------------------------------------------
__device__ float g_q[(size_t)M_ * C_];
__device__ float g_k[(size_t)M_ * KVC_];
__device__ float g_v[(size_t)M_ * KVC_];
__device__ float g_y[(size_t)M_ * C_];
__device__ float g_x[(size_t)M_ * C_];
__device__ float g_wq[(size_t)C_ * C_];
__device__ float g_wk[(size_t)C_ * KVC_];
__device__ float g_wv[(size_t)C_ * KVC_];
__device__ float g_wo[(size_t)C_ * C_];

// ---------------------------------------------------------------------------
// helpers
// ---------------------------------------------------------------------------
__device__ __forceinline__ uint32_t smem_u32(const void* p) {
    uint32_t a;
    asm("{ .reg .u64 t; cvta.to.shared.u64 t, %1; cvt.u32.u64 %0, t; }" : "=r"(a) : "l"(p));
    return a;
}

__device__ __forceinline__ float tf32r(float x) {
    unsigned u;
    asm("cvt.rna.tf32.f32 %0, %1;" : "=r"(u) : "f"(x));
    return __uint_as_float(u);
}

__device__ __forceinline__ void cp16(uint32_t s, const void* g) {
    asm volatile("cp.async.cg.shared.global [%0], [%1], 16;" :: "r"(s), "l"(g) : "memory");
}
#define CP_COMMIT() asm volatile("cp.async.commit_group;" ::: "memory")
#define CP_WAIT(n)  asm volatile("cp.async.wait_group %0;" :: "n"(n) : "memory")

__device__ __forceinline__ void mma_tf32(float* c, const float* a, const float* b) {
    const unsigned* A = reinterpret_cast<const unsigned*>(a);
    const unsigned* Bv = reinterpret_cast<const unsigned*>(b);
    asm volatile(
        "mma.sync.aligned.m16n8k8.row.col.f32.tf32.tf32.f32 "
        "{%0,%1,%2,%3}, {%4,%5,%6,%7}, {%8,%9}, {%0,%1,%2,%3};\n"
        : "+f"(c[0]), "+f"(c[1]), "+f"(c[2]), "+f"(c[3])
        : "r"(A[0]), "r"(A[1]), "r"(A[2]), "r"(A[3]), "r"(Bv[0]), "r"(Bv[1]));
}

// ---------------------------------------------------------------------------
// tf32 pre-round kernel
// ---------------------------------------------------------------------------
__global__ __launch_bounds__(256) void tf32_round_kernel(
    const float4* __restrict__ src, float4* __restrict__ dst, int n4)
{
    int i = blockIdx.x * 256 + threadIdx.x;
    if (i < n4) {
        float4 v = src[i];
        dst[i] = make_float4(tf32r(v.x), tf32r(v.y), tf32r(v.z), tf32r(v.w));
    }
}

// ---------------------------------------------------------------------------
// cp.async 4-stage pipelined tf32 GEMM mainloop.
// Tile 128x128, K-step 32, 512 threads (16 warps 4x4), warp tile 32x32.
// ---------------------------------------------------------------------------
#define A_ST 36
#define B_ST 136
#define ABUF (128 * A_ST)
#define BBUF (32 * B_ST)
#define STAGES 4
#define GEMM_SM_FLOATS (STAGES * (ABUF + BBUF))   // 143360 B
#define STAGE_ST 132

__device__ __forceinline__ void gemm_main(
    const float* __restrict__ Ab, const float* __restrict__ Bb,
    int Nb, int K, float* sm, float acc[2][4][4])
{
    float* As = sm;
    float* Bs = sm + STAGES * ABUF;
    const uint32_t sA = smem_u32(As);
    const uint32_t sB = smem_u32(Bs);

    const int tid = threadIdx.x;
    const int lane = tid & 31;
    const int wid = tid >> 5;
    const int t4 = lane >> 2;
    const int tm4 = lane & 3;
    const int wy = wid & 3;        // 4 warps along M (32 rows each)
    const int wx = wid >> 2;       // 4 warps along N (32 cols each)

    #pragma unroll
    for (int i = 0; i < 2; i++)
        #pragma unroll
        for (int j = 0; j < 4; j++)
            #pragma unroll
            for (int r = 0; r < 4; r++) acc[i][j][r] = 0.f;

    const int NT = K >> 5;

    auto load_stage = [&](int t, int slot) {
        const float* An = Ab + t * 32;
        const float* Bn = Bb + (size_t)(t * 32) * Nb;
        #pragma unroll
        for (int i = 0; i < 2; i++) {
            int idx = tid + i * 512;
            int r = idx >> 3, cg = (idx & 7) << 2;
            cp16(sA + (uint32_t)(slot * ABUF + r * A_ST + cg) * 4,
                 An + (size_t)r * K + cg);
        }
        #pragma unroll
        for (int i = 0; i < 2; i++) {
            int idx = tid + i * 512;
            int r = idx >> 5, c = (idx & 31) << 2;
            cp16(sB + (uint32_t)(slot * BBUF + r * B_ST + c) * 4,
                 Bn + (size_t)r * Nb + c);
        }
    };

    #pragma unroll
    for (int s = 0; s < STAGES - 1; s++) {
        if (s < NT) load_stage(s, s);
        CP_COMMIT();
    }

    for (int t = 0; t < NT; t++) {
        CP_WAIT(STAGES - 2);
        __syncthreads();

        int u = t + STAGES - 1;
        if (u < NT) load_stage(u, u & (STAGES - 1));
        CP_COMMIT();

        const int slot = t & (STAGES - 1);
        float* Asb = As + slot * ABUF;
        float* Bsb = Bs + slot * BBUF;
        #pragma unroll
        for (int ks = 0; ks < 32; ks += 8) {
            float afr[2][4], bfr[4][2];
            #pragma unroll
            for (int mi = 0; mi < 2; mi++) {
                int rb = wy * 32 + mi * 16;
                afr[mi][0] = Asb[(rb + t4) * A_ST + ks + tm4];
                afr[mi][1] = Asb[(rb + 8 + t4) * A_ST + ks + tm4];
                afr[mi][2] = Asb[(rb + t4) * A_ST + ks + tm4 + 4];
                afr[mi][3] = Asb[(rb + 8 + t4) * A_ST + ks + tm4 + 4];
            }
            #pragma unroll
            for (int ni = 0; ni < 4; ni++) {
                int cb = wx * 32 + ni * 8;
                bfr[ni][0] = Bsb[(ks + tm4) * B_ST + cb + t4];
                bfr[ni][1] = Bsb[(ks + tm4 + 4) * B_ST + cb + t4];
            }
            #pragma unroll
            for (int mi = 0; mi < 2; mi++)
                #pragma unroll
                for (int ni = 0; ni < 4; ni++)
                    mma_tf32(acc[mi][ni], afr[mi], bfr[ni]);
        }
    }
}

// Plain epilogue
template <bool ROUND>
__device__ __forceinline__ void epi_plain(float acc[2][4][4], float* out, int Nout)
{
    const int tid = threadIdx.x;
    const int lane = tid & 31;
    const int wid = tid >> 5;
    const int t4 = lane >> 2;
    const int tm4 = lane & 3;
    const int wy = wid & 3;
    const int wx = wid >> 2;
    #pragma unroll
    for (int mi = 0; mi < 2; mi++) {
        int row = wy * 32 + mi * 16 + t4;
        #pragma unroll
        for (int ni = 0; ni < 4; ni++) {
            int col = wx * 32 + ni * 8 + tm4 * 2;
            float a0 = acc[mi][ni][0], a1 = acc[mi][ni][1];
            float a2 = acc[mi][ni][2], a3 = acc[mi][ni][3];
            if (ROUND) { a0 = tf32r(a0); a1 = tf32r(a1); a2 = tf32r(a2); a3 = tf32r(a3); }
            *(float2*)(out + (size_t)row * Nout + col) = make_float2(a0, a1);
            *(float2*)(out + (size_t)(row + 8) * Nout + col) = make_float2(a2, a3);
        }
    }
}

// RoPE + RMSNorm epilogue (tf32-rounded output), 512 threads.
__device__ __forceinline__ void epi_rope(
    float acc[2][4][4], float* sm,
    const float* __restrict__ cs, const float* __restrict__ sn,
    float* out, int Nout, int m0)
{
    float* stage = sm;   // 128 x STAGE_ST
    const int tid = threadIdx.x;
    const int lane = tid & 31;
    const int wid = tid >> 5;
    const int t4 = lane >> 2;
    const int tm4 = lane & 3;
    const int wy = wid & 3;
    const int wx = wid >> 2;

    __syncthreads();
    #pragma unroll
    for (int mi = 0; mi < 2; mi++) {
        int row = wy * 32 + mi * 16 + t4;
        #pragma unroll
        for (int ni = 0; ni < 4; ni++) {
            int col = wx * 32 + ni * 8 + tm4 * 2;
            *(float2*)(&stage[row * STAGE_ST + col]) = make_float2(acc[mi][ni][0], acc[mi][ni][1]);
            *(float2*)(&stage[(row + 8) * STAGE_ST + col]) = make_float2(acc[mi][ni][2], acc[mi][ni][3]);
        }
    }
    __syncthreads();

    // 4 threads per row: (hf, jq) quarters; jj in [jq*32, jq*32+32)
    {
        const int r = tid >> 2;
        const int sub = tid & 3;
        const int hf = sub & 1;
        const int jq = sub >> 1;
        const int tpos = (m0 + r) & (T_ - 1);
        const float* cr = cs + tpos * 64 + jq * 32;
        const float* sr = sn + tpos * 64 + jq * 32;
        float* row = &stage[r * STAGE_ST];
        float* rin1 = row + jq * 32;
        float* rin2 = row + jq * 32 + 64;

        float ss = 0.f;
        #pragma unroll 8
        for (int j = 0; j < 32; j++) {
            float x1 = rin1[j], x2 = rin2[j];
            float c = cr[j], s = sr[j];
            float val = hf ? (x2 * c - x1 * s) : (x1 * c + x2 * s);
            ss += val * val;
        }
        ss += __shfl_xor_sync(0xffffffffu, ss, 1);
        ss += __shfl_xor_sync(0xffffffffu, ss, 2);
        float inv = rsqrtf(ss * (1.f / 128.f) + RMS_EPS);

        float* rout = row + hf * 64 + jq * 32;
        #pragma unroll 8
        for (int j = 0; j < 32; j++) {
            float x1 = rin1[j], x2 = rin2[j];
            float c = cr[j], s = sr[j];
            float val = hf ? (x2 * c - x1 * s) : (x1 * c + x2 * s);
            rout[j] = tf32r(val * inv);
        }
    }
    __syncthreads();

    // Coalesced write: each warp covers a full 128-float row; 16 warps x 8 rows
    {
        const int c4 = lane * 4;
        #pragma unroll
        for (int p = 0; p < 8; p++) {
            int row = p * 16 + wid;
            float4 v = *(const float4*)(&stage[row * STAGE_ST + c4]);
            *(float4*)(out + (size_t)row * Nout + c4) = v;
        }
    }
}

// ---------------------------------------------------------------------------
// Fused QKV projection + RoPE + RMSNorm. grid (24, 32), 512 threads.
// ---------------------------------------------------------------------------
__global__ __launch_bounds__(512, 1) void gemm_qkv(
    const float* __restrict__ x,
    const float* __restrict__ Wq, const float* __restrict__ Wk, const float* __restrict__ Wv,
    const float* __restrict__ cs, const float* __restrict__ sn,
    float* __restrict__ q, float* __restrict__ k, float* __restrict__ v)
{
    extern __shared__ float sm[];
    const int bx = blockIdx.x;
    const int m0 = blockIdx.y * 128;

    const float* Bw;
    float* outp;
    int Nb, colt;
    bool dorope;
    if (bx < 16)      { Bw = Wq; outp = q; Nb = C_;   colt = bx * 128;        dorope = true; }
    else if (bx < 20) { Bw = Wk; outp = k; Nb = KVC_; colt = (bx - 16) * 128; dorope = true; }
    else              { Bw = Wv; outp = v; Nb = KVC_; colt = (bx - 20) * 128; dorope = false; }

    float acc[2][4][4];
    gemm_main(x + (size_t)m0 * C_, Bw + colt, Nb, C_, sm, acc);

    float* out_tile = outp + (size_t)m0 * Nb + colt;
    if (dorope) epi_rope(acc, sm, cs, sn, out_tile, Nb, m0);
    else        epi_plain<true>(acc, out_tile, Nb);
}

// ---------------------------------------------------------------------------
// Output projection: out = y @ Wo. grid (16, 32), 512 threads.
// ---------------------------------------------------------------------------
__global__ __launch_bounds__(512, 1) void gemm_out(
    const float* __restrict__ y, const float* __restrict__ Wo, float* __restrict__ out)
{
    extern __shared__ float sm[];
    const int m0 = blockIdx.y * 128;
    const int colt = blockIdx.x * 128;
    float acc[2][4][4];
    gemm_main(y + (size_t)m0 * C_, Wo + colt, C_, C_, sm, acc);
    epi_plain<false>(acc, out + (size_t)m0 * C_ + colt, C_);
}

// ---------------------------------------------------------------------------
// Flash attention (causal, GQA rep=4), 512 threads (16 warps 4x4).
// S warp tile 16x16, PV warp tile 16x32. cp.async double-buffered K/V.
// ---------------------------------------------------------------------------
#define FA_BR 64
#define FA_BC 64
#define Q_ST 132
#define K_ST 132
#define V_ST 136
#define S_ST 68

#define SM_Q   0
#define SM_K   (FA_BR * Q_ST)
#define SM_V   (SM_K + 2 * FA_BC * K_ST)
#define SM_S   (SM_V + 2 * FA_BC * V_ST)
#define SM_M   (SM_S + FA_BR * S_ST)
#define SM_L   (SM_M + FA_BR)
#define SM_A   (SM_L + FA_BR)
#define FA_SMEM_FLOATS (SM_A + FA_BR)     // 189184 B

__global__ __launch_bounds__(512, 1) void flash_attn_tf32(
    const float* __restrict__ q, const float* __restrict__ k,
    const float* __restrict__ v, float* __restrict__ y)
{
    extern __shared__ float sm[];
    float* Qs = sm + SM_Q;
    float* Ks = sm + SM_K;
    float* Vs = sm + SM_V;
    float* Ss = sm + SM_S;
    float* m_s = sm + SM_M;
    float* l_s = sm + SM_L;
    float* a_s = sm + SM_A;
    const uint32_t sbase = smem_u32(sm);

    const int tid = threadIdx.x;
    const int lane = tid & 31;
    const int wid = tid >> 5;
    const int t4 = lane >> 2;
    const int tm4 = lane & 3;
    const int wy = wid & 3;      // 4 warp-rows of 16
    const int wx = wid >> 2;     // 4 warp-cols

    const int bh = blockIdx.y;
    const int b = bh >> 4;
    const int h = bh & 15;
    const int kvh = h >> 2;
    const int qt = gridDim.x - 1 - blockIdx.x;
    const int q0 = qt * FA_BR;

    const float* qbase = q + (size_t)b * T_ * C_ + h * D_;
    const float* kbase = k + (size_t)b * T_ * KVC_ + kvh * D_;
    const float* vbase = v + (size_t)b * T_ * KVC_ + kvh * D_;

    auto issue_kv = [&](int kt, int slot) {
        const float* kb = kbase + (size_t)(kt * FA_BC) * KVC_;
        const float* vb = vbase + (size_t)(kt * FA_BC) * KVC_;
        #pragma unroll
        for (int i = 0; i < 4; i++) {
            int idx = tid + i * 512;
            int r = idx >> 5;
            int c = (idx & 31) << 2;
            cp16(sbase + (uint32_t)(SM_K + slot * FA_BC * K_ST + r * K_ST + c) * 4,
                 kb + (size_t)r * KVC_ + c);
            cp16(sbase + (uint32_t)(SM_V + slot * FA_BC * V_ST + r * V_ST + c) * 4,
                 vb + (size_t)r * KVC_ + c);
        }
    };

    #pragma unroll
    for (int i = 0; i < 4; i++) {
        int idx = tid + i * 512;
        int r = idx >> 5;
        int c = (idx & 31) << 2;
        cp16(sbase + (uint32_t)(SM_Q + r * Q_ST + c) * 4,
             qbase + (size_t)(q0 + r) * C_ + c);
    }
    issue_kv(0, 0);
    CP_COMMIT();

    if (tid < FA_BR) { m_s[tid] = -INFINITY; l_s[tid] = 0.f; }

    float o[4][4];
    #pragma unroll
    for (int j = 0; j < 4; j++)
        #pragma unroll
        for (int r = 0; r < 4; r++) o[j][r] = 0.f;

    const int rb0 = wy * 16;     // warp's row base

    for (int kt = 0; kt <= qt; kt++) {
        const int slot = kt & 1;
        CP_WAIT(0);
        __syncthreads();

        if (kt < qt) { issue_kv(kt + 1, slot ^ 1); CP_COMMIT(); }

        float* Ksb = Ks + slot * FA_BC * K_ST;
        float* Vsb = Vs + slot * FA_BC * V_ST;

        // S = Q @ K^T  (warp tile 16x16)
        float sacc[2][4];
        #pragma unroll
        for (int j = 0; j < 2; j++)
            #pragma unroll
            for (int r = 0; r < 4; r++) sacc[j][r] = 0.f;

        #pragma unroll
        for (int ks = 0; ks < D_; ks += 8) {
            float afr[4], bfr[2][2];
            afr[0] = Qs[(rb0 + t4) * Q_ST + ks + tm4];
            afr[1] = Qs[(rb0 + 8 + t4) * Q_ST + ks + tm4];
            afr[2] = Qs[(rb0 + t4) * Q_ST + ks + tm4 + 4];
            afr[3] = Qs[(rb0 + 8 + t4) * Q_ST + ks + tm4 + 4];
            #pragma unroll
            for (int ni = 0; ni < 2; ni++) {
                int cb = wx * 16 + ni * 8;
                bfr[ni][0] = Ksb[(cb + t4) * K_ST + ks + tm4];
                bfr[ni][1] = Ksb[(cb + t4) * K_ST + ks + tm4 + 4];
            }
            #pragma unroll
            for (int ni = 0; ni < 2; ni++)
                mma_tf32(sacc[ni], afr, bfr[ni]);
        }

        const bool diag = (kt == qt);
        #pragma unroll
        for (int ni = 0; ni < 2; ni++) {
            int rA = rb0 + t4;
            int cA = wx * 16 + ni * 8 + tm4 * 2;
            #pragma unroll
            for (int half = 0; half < 2; half++) {
                int r = rA + half * 8;
                float v0 = sacc[ni][half * 2 + 0] * SCALE_;
                float v1 = sacc[ni][half * 2 + 1] * SCALE_;
                if (diag) {
                    if (cA > r) v0 = -INFINITY;
                    if (cA + 1 > r) v1 = -INFINITY;
                }
                *(float2*)(&Ss[r * S_ST + cA]) = make_float2(v0, v1);
            }
        }
        __syncthreads();

        // Online softmax: 8 threads per row, 8 cols each
        {
            const int srow = tid >> 3;
            const int ssub = tid & 7;
            float* Srow = Ss + srow * S_ST + ssub * 8;
            float mo = m_s[srow];
            float mx = mo;
            #pragma unroll
            for (int j = 0; j < 8; j++) mx = fmaxf(mx, Srow[j]);
            mx = fmaxf(mx, __shfl_xor_sync(0xffffffffu, mx, 1));
            mx = fmaxf(mx, __shfl_xor_sync(0xffffffffu, mx, 2));
            mx = fmaxf(mx, __shfl_xor_sync(0xffffffffu, mx, 4));
            float sum = 0.f;
            #pragma unroll
            for (int j = 0; j < 8; j++) {
                float p = __expf(Srow[j] - mx);
                Srow[j] = tf32r(p);
                sum += p;
            }
            sum += __shfl_xor_sync(0xffffffffu, sum, 1);
            sum += __shfl_xor_sync(0xffffffffu, sum, 2);
            sum += __shfl_xor_sync(0xffffffffu, sum, 4);
            if (ssub == 0) {
                float alpha = __expf(mo - mx);
                a_s[srow] = alpha;
                l_s[srow] = l_s[srow] * alpha + sum;
                m_s[srow] = mx;
            }
        }
        __syncthreads();

        // Rescale + PV (warp tile 16x32)
        {
            int rb = rb0 + t4;
            float al0 = a_s[rb];
            float al1 = a_s[rb + 8];
            #pragma unroll
            for (int ni = 0; ni < 4; ni++) {
                o[ni][0] *= al0; o[ni][1] *= al0;
                o[ni][2] *= al1; o[ni][3] *= al1;
            }
        }

        #pragma unroll
        for (int ks = 0; ks < FA_BC; ks += 8) {
            float afr[4], bfr[4][2];
            afr[0] = Ss[(rb0 + t4) * S_ST + ks + tm4];
            afr[1] = Ss[(rb0 + 8 + t4) * S_ST + ks + tm4];
            afr[2] = Ss[(rb0 + t4) * S_ST + ks + tm4 + 4];
            afr[3] = Ss[(rb0 + 8 + t4) * S_ST + ks + tm4 + 4];
            #pragma unroll
            for (int ni = 0; ni < 4; ni++) {
                int cb = wx * 32 + ni * 8;
                bfr[ni][0] = Vsb[(ks + tm4) * V_ST + cb + t4];
                bfr[ni][1] = Vsb[(ks + tm4 + 4) * V_ST + cb + t4];
            }
            #pragma unroll
            for (int ni = 0; ni < 4; ni++)
                mma_tf32(o[ni], afr, bfr[ni]);
        }
    }

    __syncthreads();
    // Epilogue
    float* ybase = y + (size_t)b * T_ * C_ + h * D_;
    {
        int rb = rb0 + t4;
        float inv0 = 1.f / l_s[rb];
        float inv1 = 1.f / l_s[rb + 8];
        #pragma unroll
        for (int ni = 0; ni < 4; ni++) {
            int col = wx * 32 + ni * 8 + tm4 * 2;
            float* d0 = ybase + (size_t)(q0 + rb) * C_ + col;
            float* d1 = ybase + (size_t)(q0 + rb + 8) * C_ + col;
            *(float2*)d0 = make_float2(tf32r(o[ni][0] * inv0), tf32r(o[ni][1] * inv0));
            *(float2*)d1 = make_float2(tf32r(o[ni][2] * inv1), tf32r(o[ni][3] * inv1));
        }
    }
}

// ---------------------------------------------------------------------------
// Launch
// ---------------------------------------------------------------------------
extern "C" void kernel_launch(void* const* d_in, const int* in_sizes, int n_in,
                              void* d_out, int out_size)
{
    const float* x   = (const float*)d_in[0];
    const float* cs  = (const float*)d_in[1];
    const float* sn  = (const float*)d_in[2];
    const float* Wq  = (const float*)d_in[3];
    const float* Wk  = (const float*)d_in[4];
    const float* Wv  = (const float*)d_in[5];
    const float* Wo  = (const float*)d_in[6];
    float* out = (float*)d_out;

    float *qp, *kp, *vp, *yp, *xp, *wqp, *wkp, *wvp, *wop;
    cudaGetSymbolAddress((void**)&qp, g_q);
    cudaGetSymbolAddress((void**)&kp, g_k);
    cudaGetSymbolAddress((void**)&vp, g_v);
    cudaGetSymbolAddress((void**)&yp, g_y);
    cudaGetSymbolAddress((void**)&xp, g_x);
    cudaGetSymbolAddress((void**)&wqp, g_wq);
    cudaGetSymbolAddress((void**)&wkp, g_wk);
    cudaGetSymbolAddress((void**)&wvp, g_wv);
    cudaGetSymbolAddress((void**)&wop, g_wo);

    const int gemm_smem = GEMM_SM_FLOATS * 4;
    cudaFuncSetAttribute(gemm_qkv, cudaFuncAttributeMaxDynamicSharedMemorySize, gemm_smem);
    cudaFuncSetAttribute(gemm_out, cudaFuncAttributeMaxDynamicSharedMemorySize, gemm_smem);
    const int fa_smem = FA_SMEM_FLOATS * 4;
    cudaFuncSetAttribute(flash_attn_tf32, cudaFuncAttributeMaxDynamicSharedMemorySize, fa_smem);

    dim3 blk256(256), blk512(512);
    // Pre-round inputs to tf32
    {
        int n4;
        n4 = (M_ * C_) / 4;
        tf32_round_kernel<<<(n4 + 255) / 256, blk256>>>((const float4*)x, (float4*)xp, n4);
        n4 = (C_ * C_) / 4;
        tf32_round_kernel<<<(n4 + 255) / 256, blk256>>>((const float4*)Wq, (float4*)wqp, n4);
        n4 = (C_ * KVC_) / 4;
        tf32_round_kernel<<<(n4 + 255) / 256, blk256>>>((const float4*)Wk, (float4*)wkp, n4);
        tf32_round_kernel<<<(n4 + 255) / 256, blk256>>>((const float4*)Wv, (float4*)wvp, n4);
        n4 = (C_ * C_) / 4;
        tf32_round_kernel<<<(n4 + 255) / 256, blk256>>>((const float4*)Wo, (float4*)wop, n4);
    }
    // Fused Q/K/V projections + RoPE + RMSNorm
    gemm_qkv<<<dim3(24, M_ / 128), blk512, gemm_smem>>>(xp, wqp, wkp, wvp, cs, sn, qp, kp, vp);
    // Attention
    flash_attn_tf32<<<dim3(T_ / FA_BR, B_ * H_), blk512, fa_smem>>>(qp, kp, vp, yp);
    // Output projection
    gemm_out<<<dim3(C_ / 128, M_ / 128), blk512, gemm_smem>>>(yp, wop, out);
}

// round 11
// speedup vs baseline: 1.1753x; 1.1753x over previous
#include <cuda_runtime.h>
#include <cuda_bf16.h>
#include <math.h>
#include <stdint.h>

// Problem constants
#define B_ 2
#define T_ 2048
#define C_ 2048
#define H_ 16
#define KVH_ 4
#define D_ 128
#define M_ (B_ * T_)          // 4096
#define KVC_ (KVH_ * D_)      // 512
#define SCALE_ 0.08838834764831845f
#define RMS_EPS 1.1920929e-07f

// ---------------------------------------------------------------------------
// Scratch (device globals; no allocation allowed)
// ---------------------------------------------------------------------------
__device__ float g_q[(size_t)M_ * C_];
__device__ float g_k[(size_t)M_ * KVC_];
__device__ float g_v[(size_t)M_ * KVC_];
__device__ float g_y[(size_t)M_ * C_];
__device__ float g_x[(size_t)M_ * C_];
__device__ float g_wq[(size_t)C_ * C_];
__device__ float g_wk[(size_t)C_ * KVC_];
__device__ float g_wv[(size_t)C_ * KVC_];
__device__ float g_wo[(size_t)C_ * C_];

// ---------------------------------------------------------------------------
// helpers
// ---------------------------------------------------------------------------
__device__ __forceinline__ uint32_t smem_u32(const void* p) {
    uint32_t a;
    asm("{ .reg .u64 t; cvta.to.shared.u64 t, %1; cvt.u32.u64 %0, t; }" : "=r"(a) : "l"(p));
    return a;
}

__device__ __forceinline__ float tf32r(float x) {
    unsigned u;
    asm("cvt.rna.tf32.f32 %0, %1;" : "=r"(u) : "f"(x));
    return __uint_as_float(u);
}

__device__ __forceinline__ void cp16(uint32_t s, const void* g) {
    asm volatile("cp.async.cg.shared.global [%0], [%1], 16;" :: "r"(s), "l"(g) : "memory");
}
#define CP_COMMIT() asm volatile("cp.async.commit_group;" ::: "memory")
#define CP_WAIT(n)  asm volatile("cp.async.wait_group %0;" :: "n"(n) : "memory")

__device__ __forceinline__ void mma_tf32(float* c, const float* a, const float* b) {
    const unsigned* A = reinterpret_cast<const unsigned*>(a);
    const unsigned* Bv = reinterpret_cast<const unsigned*>(b);
    asm volatile(
        "mma.sync.aligned.m16n8k8.row.col.f32.tf32.tf32.f32 "
        "{%0,%1,%2,%3}, {%4,%5,%6,%7}, {%8,%9}, {%0,%1,%2,%3};\n"
        : "+f"(c[0]), "+f"(c[1]), "+f"(c[2]), "+f"(c[3])
        : "r"(A[0]), "r"(A[1]), "r"(A[2]), "r"(A[3]), "r"(Bv[0]), "r"(Bv[1]));
}

// ---------------------------------------------------------------------------
// tf32 pre-round kernel
// ---------------------------------------------------------------------------
__global__ __launch_bounds__(256) void tf32_round_kernel(
    const float4* __restrict__ src, float4* __restrict__ dst, int n4)
{
    int i = blockIdx.x * 256 + threadIdx.x;
    if (i < n4) {
        float4 v = src[i];
        dst[i] = make_float4(tf32r(v.x), tf32r(v.y), tf32r(v.z), tf32r(v.w));
    }
}

// ---------------------------------------------------------------------------
// cp.async 3-stage pipelined tf32 GEMM mainloop.
// Tile 128x128, K-step 32, 256 threads (8 warps 2x4), warp tile 64x32.
// smem = 3*(4608+4352)*4 = 107520 B  -> 2 CTAs/SM.
// ---------------------------------------------------------------------------
#define A_ST 36
#define B_ST 136
#define ABUF (128 * A_ST)
#define BBUF (32 * B_ST)
#define STAGES 3
#define GEMM_SM_FLOATS (STAGES * (ABUF + BBUF))   // 26880 floats = 107520 B
#define STAGE_ST 132

__device__ __forceinline__ void gemm_main(
    const float* __restrict__ Ab, const float* __restrict__ Bb,
    int Nb, int K, float* sm, float acc[4][4][4])
{
    float* As = sm;
    float* Bs = sm + STAGES * ABUF;
    const uint32_t sA = smem_u32(As);
    const uint32_t sB = smem_u32(Bs);

    const int tid = threadIdx.x;
    const int lane = tid & 31;
    const int wid = tid >> 5;
    const int t4 = lane >> 2;
    const int tm4 = lane & 3;
    const int wy = wid & 1;
    const int wx = wid >> 1;

    #pragma unroll
    for (int i = 0; i < 4; i++)
        #pragma unroll
        for (int j = 0; j < 4; j++)
            #pragma unroll
            for (int r = 0; r < 4; r++) acc[i][j][r] = 0.f;

    const int NT = K >> 5;

    auto load_stage = [&](int t, int slot) {
        const float* An = Ab + t * 32;
        const float* Bn = Bb + (size_t)(t * 32) * Nb;
        #pragma unroll
        for (int i = 0; i < 4; i++) {
            int idx = tid + i * 256;
            int r = idx >> 3, cg = (idx & 7) << 2;
            cp16(sA + (uint32_t)(slot * ABUF + r * A_ST + cg) * 4,
                 An + (size_t)r * K + cg);
        }
        #pragma unroll
        for (int i = 0; i < 4; i++) {
            int idx = tid + i * 256;
            int r = idx >> 5, c = (idx & 31) << 2;
            cp16(sB + (uint32_t)(slot * BBUF + r * B_ST + c) * 4,
                 Bn + (size_t)r * Nb + c);
        }
    };

    // Prologue: stages 0..STAGES-2
    #pragma unroll
    for (int s = 0; s < STAGES - 1; s++) {
        if (s < NT) load_stage(s, s);
        CP_COMMIT();
    }

    int slot = 0;
    for (int t = 0; t < NT; t++) {
        CP_WAIT(STAGES - 2);
        __syncthreads();

        int u = t + STAGES - 1;
        int uslot = slot + STAGES - 1;
        if (uslot >= STAGES) uslot -= STAGES;
        if (u < NT) load_stage(u, uslot);
        CP_COMMIT();

        float* Asb = As + slot * ABUF;
        float* Bsb = Bs + slot * BBUF;
        #pragma unroll
        for (int ks = 0; ks < 32; ks += 8) {
            float afr[4][4], bfr[4][2];
            #pragma unroll
            for (int mi = 0; mi < 4; mi++) {
                int rb = wy * 64 + mi * 16;
                afr[mi][0] = Asb[(rb + t4) * A_ST + ks + tm4];
                afr[mi][1] = Asb[(rb + 8 + t4) * A_ST + ks + tm4];
                afr[mi][2] = Asb[(rb + t4) * A_ST + ks + tm4 + 4];
                afr[mi][3] = Asb[(rb + 8 + t4) * A_ST + ks + tm4 + 4];
            }
            #pragma unroll
            for (int ni = 0; ni < 4; ni++) {
                int cb = wx * 32 + ni * 8;
                bfr[ni][0] = Bsb[(ks + tm4) * B_ST + cb + t4];
                bfr[ni][1] = Bsb[(ks + tm4 + 4) * B_ST + cb + t4];
            }
            #pragma unroll
            for (int mi = 0; mi < 4; mi++)
                #pragma unroll
                for (int ni = 0; ni < 4; ni++)
                    mma_tf32(acc[mi][ni], afr[mi], bfr[ni]);
        }
        if (++slot == STAGES) slot = 0;
    }
}

// Plain epilogue
template <bool ROUND>
__device__ __forceinline__ void epi_plain(float acc[4][4][4], float* out, int Nout)
{
    const int tid = threadIdx.x;
    const int lane = tid & 31;
    const int wid = tid >> 5;
    const int t4 = lane >> 2;
    const int tm4 = lane & 3;
    const int wy = wid & 1;
    const int wx = wid >> 1;
    #pragma unroll
    for (int mi = 0; mi < 4; mi++) {
        int row = wy * 64 + mi * 16 + t4;
        #pragma unroll
        for (int ni = 0; ni < 4; ni++) {
            int col = wx * 32 + ni * 8 + tm4 * 2;
            float a0 = acc[mi][ni][0], a1 = acc[mi][ni][1];
            float a2 = acc[mi][ni][2], a3 = acc[mi][ni][3];
            if (ROUND) { a0 = tf32r(a0); a1 = tf32r(a1); a2 = tf32r(a2); a3 = tf32r(a3); }
            *(float2*)(out + (size_t)row * Nout + col) = make_float2(a0, a1);
            *(float2*)(out + (size_t)(row + 8) * Nout + col) = make_float2(a2, a3);
        }
    }
}

// RoPE + RMSNorm epilogue (stores tf32-rounded)
__device__ __forceinline__ void epi_rope(
    float acc[4][4][4], float* sm,
    const float* __restrict__ cs, const float* __restrict__ sn,
    float* out, int Nout, int m0)
{
    float* stage = sm;   // 128 x STAGE_ST floats (fits in 107520B? 128*132*4=67584B yes)
    const int tid = threadIdx.x;
    const int lane = tid & 31;
    const int wid = tid >> 5;
    const int t4 = lane >> 2;
    const int tm4 = lane & 3;
    const int wy = wid & 1;
    const int wx = wid >> 1;

    __syncthreads();
    #pragma unroll
    for (int mi = 0; mi < 4; mi++) {
        int row = wy * 64 + mi * 16 + t4;
        #pragma unroll
        for (int ni = 0; ni < 4; ni++) {
            int col = wx * 32 + ni * 8 + tm4 * 2;
            *(float2*)(&stage[row * STAGE_ST + col]) = make_float2(acc[mi][ni][0], acc[mi][ni][1]);
            *(float2*)(&stage[(row + 8) * STAGE_ST + col]) = make_float2(acc[mi][ni][2], acc[mi][ni][3]);
        }
    }
    __syncthreads();

    {
        const int r = tid >> 1;
        const int hf = tid & 1;
        const int tpos = (m0 + r) & (T_ - 1);
        const float* cr = cs + tpos * 64;
        const float* sr = sn + tpos * 64;
        float* row = &stage[r * STAGE_ST];

        float ss = 0.f;
        #pragma unroll 8
        for (int j = 0; j < 64; j++) {
            float x1 = row[j], x2 = row[j + 64];
            float c = cr[j], s = sr[j];
            float val = hf ? (x2 * c - x1 * s) : (x1 * c + x2 * s);
            ss += val * val;
        }
        ss += __shfl_xor_sync(0xffffffffu, ss, 1);
        float inv = rsqrtf(ss * (1.f / 128.f) + RMS_EPS);

        #pragma unroll 8
        for (int j = 0; j < 64; j++) {
            float x1 = row[j], x2 = row[j + 64];
            float c = cr[j], s = sr[j];
            float val = hf ? (x2 * c - x1 * s) : (x1 * c + x2 * s);
            row[hf * 64 + j] = tf32r(val * inv);
        }
    }
    __syncthreads();

    {
        const int c4 = lane * 4;
        const int rb = tid >> 5;
        #pragma unroll
        for (int p = 0; p < 16; p++) {
            int row = p * 8 + rb;
            float4 v = *(const float4*)(&stage[row * STAGE_ST + c4]);
            *(float4*)(out + (size_t)row * Nout + c4) = v;
        }
    }
}

// ---------------------------------------------------------------------------
// Fused QKV projection + RoPE + RMSNorm. grid (24, 32), 256 threads, 2 CTA/SM.
// ---------------------------------------------------------------------------
__global__ __launch_bounds__(256, 2) void gemm_qkv(
    const float* __restrict__ x,
    const float* __restrict__ Wq, const float* __restrict__ Wk, const float* __restrict__ Wv,
    const float* __restrict__ cs, const float* __restrict__ sn,
    float* __restrict__ q, float* __restrict__ k, float* __restrict__ v)
{
    extern __shared__ float sm[];
    const int bx = blockIdx.x;
    const int m0 = blockIdx.y * 128;

    const float* Bw;
    float* outp;
    int Nb, colt;
    bool dorope;
    if (bx < 16)      { Bw = Wq; outp = q; Nb = C_;   colt = bx * 128;        dorope = true; }
    else if (bx < 20) { Bw = Wk; outp = k; Nb = KVC_; colt = (bx - 16) * 128; dorope = true; }
    else              { Bw = Wv; outp = v; Nb = KVC_; colt = (bx - 20) * 128; dorope = false; }

    float acc[4][4][4];
    gemm_main(x + (size_t)m0 * C_, Bw + colt, Nb, C_, sm, acc);

    float* out_tile = outp + (size_t)m0 * Nb + colt;
    if (dorope) epi_rope(acc, sm, cs, sn, out_tile, Nb, m0);
    else        epi_plain<true>(acc, out_tile, Nb);
}

// ---------------------------------------------------------------------------
// Output projection: out = y @ Wo. grid (16, 32), 256 threads, 2 CTA/SM.
// ---------------------------------------------------------------------------
__global__ __launch_bounds__(256, 2) void gemm_out(
    const float* __restrict__ y, const float* __restrict__ Wo, float* __restrict__ out)
{
    extern __shared__ float sm[];
    const int m0 = blockIdx.y * 128;
    const int colt = blockIdx.x * 128;
    float acc[4][4][4];
    gemm_main(y + (size_t)m0 * C_, Wo + colt, C_, C_, sm, acc);
    epi_plain<false>(acc, out + (size_t)m0 * C_ + colt, C_);
}

// ---------------------------------------------------------------------------
// Flash attention (causal, GQA rep=4), tf32 mma, cp.async double-buffered K/V.
// 256 threads (8 warps 2x4). Unchanged from R9.
// ---------------------------------------------------------------------------
#define FA_BR 64
#define FA_BC 64
#define Q_ST 132
#define K_ST 132
#define V_ST 136
#define S_ST 68

#define SM_Q   0
#define SM_K   (FA_BR * Q_ST)
#define SM_V   (SM_K + 2 * FA_BC * K_ST)
#define SM_S   (SM_V + 2 * FA_BC * V_ST)
#define SM_M   (SM_S + FA_BR * S_ST)
#define SM_L   (SM_M + FA_BR)
#define SM_A   (SM_L + FA_BR)
#define FA_SMEM_FLOATS (SM_A + FA_BR)     // 189184 B

__global__ __launch_bounds__(256, 1) void flash_attn_tf32(
    const float* __restrict__ q, const float* __restrict__ k,
    const float* __restrict__ v, float* __restrict__ y)
{
    extern __shared__ float sm[];
    float* Qs = sm + SM_Q;
    float* Ks = sm + SM_K;
    float* Vs = sm + SM_V;
    float* Ss = sm + SM_S;
    float* m_s = sm + SM_M;
    float* l_s = sm + SM_L;
    float* a_s = sm + SM_A;
    const uint32_t sbase = smem_u32(sm);

    const int tid = threadIdx.x;
    const int lane = tid & 31;
    const int wid = tid >> 5;
    const int t4 = lane >> 2;
    const int tm4 = lane & 3;
    const int wy = wid & 1;
    const int wx = wid >> 1;

    const int bh = blockIdx.y;
    const int b = bh >> 4;
    const int h = bh & 15;
    const int kvh = h >> 2;
    const int qt = gridDim.x - 1 - blockIdx.x;
    const int q0 = qt * FA_BR;

    const float* qbase = q + (size_t)b * T_ * C_ + h * D_;
    const float* kbase = k + (size_t)b * T_ * KVC_ + kvh * D_;
    const float* vbase = v + (size_t)b * T_ * KVC_ + kvh * D_;

    auto issue_kv = [&](int kt, int slot) {
        const float* kb = kbase + (size_t)(kt * FA_BC) * KVC_;
        const float* vb = vbase + (size_t)(kt * FA_BC) * KVC_;
        #pragma unroll
        for (int i = 0; i < 8; i++) {
            int idx = tid + i * 256;
            int r = idx >> 5;
            int c = (idx & 31) << 2;
            cp16(sbase + (uint32_t)(SM_K + slot * FA_BC * K_ST + r * K_ST + c) * 4,
                 kb + (size_t)r * KVC_ + c);
            cp16(sbase + (uint32_t)(SM_V + slot * FA_BC * V_ST + r * V_ST + c) * 4,
                 vb + (size_t)r * KVC_ + c);
        }
    };

    // Prologue: Q + KV(0)
    #pragma unroll
    for (int i = 0; i < 8; i++) {
        int idx = tid + i * 256;
        int r = idx >> 5;
        int c = (idx & 31) << 2;
        cp16(sbase + (uint32_t)(SM_Q + r * Q_ST + c) * 4,
             qbase + (size_t)(q0 + r) * C_ + c);
    }
    issue_kv(0, 0);
    CP_COMMIT();

    if (tid < FA_BR) { m_s[tid] = -INFINITY; l_s[tid] = 0.f; }

    float o[2][4][4];
    #pragma unroll
    for (int i = 0; i < 2; i++)
        #pragma unroll
        for (int j = 0; j < 4; j++)
            #pragma unroll
            for (int r = 0; r < 4; r++) o[i][j][r] = 0.f;

    for (int kt = 0; kt <= qt; kt++) {
        const int slot = kt & 1;
        CP_WAIT(0);
        __syncthreads();

        if (kt < qt) { issue_kv(kt + 1, slot ^ 1); CP_COMMIT(); }

        float* Ksb = Ks + slot * FA_BC * K_ST;
        float* Vsb = Vs + slot * FA_BC * V_ST;

        // S = Q @ K^T
        float sacc[2][2][4];
        #pragma unroll
        for (int i = 0; i < 2; i++)
            #pragma unroll
            for (int j = 0; j < 2; j++)
                #pragma unroll
                for (int r = 0; r < 4; r++) sacc[i][j][r] = 0.f;

        #pragma unroll
        for (int ks = 0; ks < D_; ks += 8) {
            float afr[2][4], bfr[2][2];
            #pragma unroll
            for (int mi = 0; mi < 2; mi++) {
                int rb = wy * 32 + mi * 16;
                afr[mi][0] = Qs[(rb + t4) * Q_ST + ks + tm4];
                afr[mi][1] = Qs[(rb + 8 + t4) * Q_ST + ks + tm4];
                afr[mi][2] = Qs[(rb + t4) * Q_ST + ks + tm4 + 4];
                afr[mi][3] = Qs[(rb + 8 + t4) * Q_ST + ks + tm4 + 4];
            }
            #pragma unroll
            for (int ni = 0; ni < 2; ni++) {
                int cb = wx * 16 + ni * 8;
                bfr[ni][0] = Ksb[(cb + t4) * K_ST + ks + tm4];
                bfr[ni][1] = Ksb[(cb + t4) * K_ST + ks + tm4 + 4];
            }
            #pragma unroll
            for (int mi = 0; mi < 2; mi++)
                #pragma unroll
                for (int ni = 0; ni < 2; ni++)
                    mma_tf32(sacc[mi][ni], afr[mi], bfr[ni]);
        }

        const bool diag = (kt == qt);
        #pragma unroll
        for (int mi = 0; mi < 2; mi++) {
            #pragma unroll
            for (int ni = 0; ni < 2; ni++) {
                int rA = wy * 32 + mi * 16 + t4;
                int cA = wx * 16 + ni * 8 + tm4 * 2;
                #pragma unroll
                for (int half = 0; half < 2; half++) {
                    int r = rA + half * 8;
                    float v0 = sacc[mi][ni][half * 2 + 0] * SCALE_;
                    float v1 = sacc[mi][ni][half * 2 + 1] * SCALE_;
                    if (diag) {
                        if (cA > r) v0 = -INFINITY;
                        if (cA + 1 > r) v1 = -INFINITY;
                    }
                    *(float2*)(&Ss[r * S_ST + cA]) = make_float2(v0, v1);
                }
            }
        }
        __syncthreads();

        // Online softmax: 4 threads per row
        {
            const int srow = tid >> 2;
            const int ssub = tid & 3;
            float* Srow = Ss + srow * S_ST + ssub * 16;
            float mo = m_s[srow];
            float mx = mo;
            #pragma unroll
            for (int j = 0; j < 16; j++) mx = fmaxf(mx, Srow[j]);
            mx = fmaxf(mx, __shfl_xor_sync(0xffffffffu, mx, 1));
            mx = fmaxf(mx, __shfl_xor_sync(0xffffffffu, mx, 2));
            float sum = 0.f;
            #pragma unroll
            for (int j = 0; j < 16; j++) {
                float p = __expf(Srow[j] - mx);
                Srow[j] = tf32r(p);
                sum += p;
            }
            sum += __shfl_xor_sync(0xffffffffu, sum, 1);
            sum += __shfl_xor_sync(0xffffffffu, sum, 2);
            if (ssub == 0) {
                float alpha = __expf(mo - mx);
                a_s[srow] = alpha;
                l_s[srow] = l_s[srow] * alpha + sum;
                m_s[srow] = mx;
            }
        }
        __syncthreads();

        // Rescale + PV
        #pragma unroll
        for (int mi = 0; mi < 2; mi++) {
            int rb = wy * 32 + mi * 16 + t4;
            float al0 = a_s[rb];
            float al1 = a_s[rb + 8];
            #pragma unroll
            for (int ni = 0; ni < 4; ni++) {
                o[mi][ni][0] *= al0; o[mi][ni][1] *= al0;
                o[mi][ni][2] *= al1; o[mi][ni][3] *= al1;
            }
        }

        #pragma unroll
        for (int ks = 0; ks < FA_BC; ks += 8) {
            float afr[2][4], bfr[4][2];
            #pragma unroll
            for (int mi = 0; mi < 2; mi++) {
                int rb = wy * 32 + mi * 16;
                afr[mi][0] = Ss[(rb + t4) * S_ST + ks + tm4];
                afr[mi][1] = Ss[(rb + 8 + t4) * S_ST + ks + tm4];
                afr[mi][2] = Ss[(rb + t4) * S_ST + ks + tm4 + 4];
                afr[mi][3] = Ss[(rb + 8 + t4) * S_ST + ks + tm4 + 4];
            }
            #pragma unroll
            for (int ni = 0; ni < 4; ni++) {
                int cb = wx * 32 + ni * 8;
                bfr[ni][0] = Vsb[(ks + tm4) * V_ST + cb + t4];
                bfr[ni][1] = Vsb[(ks + tm4 + 4) * V_ST + cb + t4];
            }
            #pragma unroll
            for (int mi = 0; mi < 2; mi++)
                #pragma unroll
                for (int ni = 0; ni < 4; ni++)
                    mma_tf32(o[mi][ni], afr[mi], bfr[ni]);
        }
    }

    __syncthreads();
    // Epilogue: divide by l, write y (tf32-rounded for gemm_out)
    float* ybase = y + (size_t)b * T_ * C_ + h * D_;
    #pragma unroll
    for (int mi = 0; mi < 2; mi++) {
        int rb = wy * 32 + mi * 16 + t4;
        float inv0 = 1.f / l_s[rb];
        float inv1 = 1.f / l_s[rb + 8];
        #pragma unroll
        for (int ni = 0; ni < 4; ni++) {
            int col = wx * 32 + ni * 8 + tm4 * 2;
            float* d0 = ybase + (size_t)(q0 + rb) * C_ + col;
            float* d1 = ybase + (size_t)(q0 + rb + 8) * C_ + col;
            *(float2*)d0 = make_float2(tf32r(o[mi][ni][0] * inv0), tf32r(o[mi][ni][1] * inv0));
            *(float2*)d1 = make_float2(tf32r(o[mi][ni][2] * inv1), tf32r(o[mi][ni][3] * inv1));
        }
    }
}

// ---------------------------------------------------------------------------
// Launch
// ---------------------------------------------------------------------------
extern "C" void kernel_launch(void* const* d_in, const int* in_sizes, int n_in,
                              void* d_out, int out_size)
{
    const float* x   = (const float*)d_in[0];
    const float* cs  = (const float*)d_in[1];
    const float* sn  = (const float*)d_in[2];
    const float* Wq  = (const float*)d_in[3];
    const float* Wk  = (const float*)d_in[4];
    const float* Wv  = (const float*)d_in[5];
    const float* Wo  = (const float*)d_in[6];
    float* out = (float*)d_out;

    float *qp, *kp, *vp, *yp, *xp, *wqp, *wkp, *wvp, *wop;
    cudaGetSymbolAddress((void**)&qp, g_q);
    cudaGetSymbolAddress((void**)&kp, g_k);
    cudaGetSymbolAddress((void**)&vp, g_v);
    cudaGetSymbolAddress((void**)&yp, g_y);
    cudaGetSymbolAddress((void**)&xp, g_x);
    cudaGetSymbolAddress((void**)&wqp, g_wq);
    cudaGetSymbolAddress((void**)&wkp, g_wk);
    cudaGetSymbolAddress((void**)&wvp, g_wv);
    cudaGetSymbolAddress((void**)&wop, g_wo);

    const int gemm_smem = GEMM_SM_FLOATS * 4;   // 107520 B
    cudaFuncSetAttribute(gemm_qkv, cudaFuncAttributeMaxDynamicSharedMemorySize, gemm_smem);
    cudaFuncSetAttribute(gemm_out, cudaFuncAttributeMaxDynamicSharedMemorySize, gemm_smem);
    const int fa_smem = FA_SMEM_FLOATS * 4;     // 189184 B
    cudaFuncSetAttribute(flash_attn_tf32, cudaFuncAttributeMaxDynamicSharedMemorySize, fa_smem);

    dim3 blk256(256);
    // Pre-round inputs to tf32
    {
        int n4;
        n4 = (M_ * C_) / 4;
        tf32_round_kernel<<<(n4 + 255) / 256, blk256>>>((const float4*)x, (float4*)xp, n4);
        n4 = (C_ * C_) / 4;
        tf32_round_kernel<<<(n4 + 255) / 256, blk256>>>((const float4*)Wq, (float4*)wqp, n4);
        n4 = (C_ * KVC_) / 4;
        tf32_round_kernel<<<(n4 + 255) / 256, blk256>>>((const float4*)Wk, (float4*)wkp, n4);
        tf32_round_kernel<<<(n4 + 255) / 256, blk256>>>((const float4*)Wv, (float4*)wvp, n4);
        n4 = (C_ * C_) / 4;
        tf32_round_kernel<<<(n4 + 255) / 256, blk256>>>((const float4*)Wo, (float4*)wop, n4);
    }
    // Fused Q/K/V projections + RoPE + RMSNorm
    gemm_qkv<<<dim3(24, M_ / 128), blk256, gemm_smem>>>(xp, wqp, wkp, wvp, cs, sn, qp, kp, vp);
    // Attention
    flash_attn_tf32<<<dim3(T_ / FA_BR, B_ * H_), blk256, fa_smem>>>(qp, kp, vp, yp);
    // Output projection
    gemm_out<<<dim3(C_ / 128, M_ / 128), blk256, gemm_smem>>>(yp, wop, out);
}